// round 15
// baseline (speedup 1.0000x reference)
#include <cuda_runtime.h>

typedef unsigned long long u64;

#define TW 64
#define TH 64
#define IW 74                   // TW + 10 halo
#define PS 65                   // transposed plane stride (odd)
#define NTHREADS 512

#define IMG_H 768
#define IMG_W 768
#define OUT_H 758
#define OUT_W 758
#define NBATCH 16
#define NCH 3

// smem: sM, sE: [IW][PS] u64 = 76960 B (2 blocks/SM: 154KB of 228KB)
#define SMEM_BYTES (IW * PS * (8 + 8))

__device__ float g_acc[NBATCH];

// Gaussian(sigma=1.5, win=11)
#define W0 0.00102838f
#define W1 0.00759880f
#define W2 0.03600077f
#define W3 0.10936070f
#define W4 0.21300553f
#define W5 0.26601172f

__device__ __forceinline__ u64 pack2(float lo, float hi) {
    u64 r; asm("mov.b64 %0, {%1,%2};" : "=l"(r) : "f"(lo), "f"(hi)); return r;
}
__device__ __forceinline__ void unpack2(u64 v, float& lo, float& hi) {
    asm("mov.b64 {%0,%1}, %2;" : "=f"(lo), "=f"(hi) : "l"(v));
}
__device__ __forceinline__ u64 fma2(u64 a, u64 b, u64 c) {
    u64 d; asm("fma.rn.f32x2 %0, %1, %2, %3;" : "=l"(d) : "l"(a), "l"(b), "l"(c));
    return d;
}
__device__ __forceinline__ u64 mul2(u64 a, u64 b) {
    u64 d; asm("mul.rn.f32x2 %0, %1, %2;" : "=l"(d) : "l"(a), "l"(b));
    return d;
}
__device__ __forceinline__ u64 add2(u64 a, u64 b) {
    u64 d; asm("add.rn.f32x2 %0, %1, %2;" : "=l"(d) : "l"(a), "l"(b));
    return d;
}

// folded symmetric 11-tap packed chain
#define CHAIN2(w, j) ({                                        \
    u64 acc_ = mul2(C5p, (w)[(j) + 5]);                        \
    acc_ = fma2(C4p, add2((w)[(j) + 4], (w)[(j) + 6]), acc_);  \
    acc_ = fma2(C3p, add2((w)[(j) + 3], (w)[(j) + 7]), acc_);  \
    acc_ = fma2(C2p, add2((w)[(j) + 2], (w)[(j) + 8]), acc_);  \
    acc_ = fma2(C1p, add2((w)[(j) + 1], (w)[(j) + 9]), acc_);  \
    acc_ = fma2(C0p, add2((w)[(j)],     (w)[(j) + 10]), acc_); \
    acc_; })

__global__ void ssim_zero_kernel() {
    if (threadIdx.x < NBATCH) g_acc[threadIdx.x] = 0.0f;
}
__global__ void ssim_dummy1_kernel() {}
__global__ void ssim_dummy2_kernel() {}
__global__ void ssim_dummy3_kernel() {}

__global__ void ssim_finalize_kernel(float* __restrict__ out) {
    if (threadIdx.x < NBATCH)
        out[threadIdx.x] = g_acc[threadIdx.x] *
            (1.0f / (float)(NCH * OUT_H * OUT_W));
}

template <bool EDGE>
__device__ __forceinline__ float ssim_tile(const float* __restrict__ Xp,
                                           const float* __restrict__ Yp,
                                           u64* sM, u64* sE,
                                           int ox0, int oy0, int tid) {
    const u64 C0p = pack2(W0, W0), C1p = pack2(W1, W1), C2p = pack2(W2, W2);
    const u64 C3p = pack2(W3, W3), C4p = pack2(W4, W4), C5p = pack2(W5, W5);

    // ---- pass 1: VERTICAL blur in (s,d)=(x+y, x-y) basis, 8 outputs/task ----
    // task: column c, 8 output rows from r0.  IW*(TH/8) = 592 tasks.
    for (int t = tid; t < IW * (TH / 8); t += NTHREADS) {
        int c  = t % IW;
        int r0 = (t / IW) * 8;

        u64 w[18];
        if (EDGE) {
            int gx = min(ox0 + c, IMG_W - 1);   // clamp: OOB feeds discarded outputs only
            #pragma unroll
            for (int i = 0; i < 18; i++) {
                int gy = min(oy0 + r0 + i, IMG_H - 1);
                int g = gy * IMG_W + gx;
                float xv = __ldg(Xp + g), yv = __ldg(Yp + g);
                w[i] = pack2(xv + yv, xv - yv);
            }
        } else {
            int g = (oy0 + r0) * IMG_W + (ox0 + c);
            #pragma unroll
            for (int i = 0; i < 18; i++) {
                float xv = __ldg(Xp + g), yv = __ldg(Yp + g);
                w[i] = pack2(xv + yv, xv - yv);
                g += IMG_W;
            }
        }

        // M stream (mu_s, mu_d)
        #pragma unroll
        for (int j = 0; j < 8; j++)
            sM[c * PS + r0 + j] = CHAIN2(w, j);

        // squares in place: (s^2, d^2)
        #pragma unroll
        for (int i = 0; i < 18; i++) w[i] = mul2(w[i], w[i]);

        // E stream (E[s^2], E[d^2])
        #pragma unroll
        for (int j = 0; j < 8; j++)
            sE[c * PS + r0 + j] = CHAIN2(w, j);
    }
    __syncthreads();

    // ---- pass 2: HORIZONTAL blur, stream-sequential, 8 outputs/thread ----
    // exactly NTHREADS tasks: r = tid&63 (0..63), c0 = (tid>>6)*8 (0..56).
    const float K1 = 0.0001f;        // C1
    const float K2 = 0.0009f;        // C2
    const float EPSV = 1e-8f;

    const int r  = tid & 63;
    const int c0 = (tid >> 6) * 8;

    u64 win[18];
    float q[8], rr[8];               // mu_s^2, mu_d^2 per output

    // --- M phase: window loads interleaved with chain computes ---
    #pragma unroll
    for (int i = 0; i < 11; i++) win[i] = sM[(c0 + i) * PS + r];
    #pragma unroll
    for (int j = 0; j < 8; j++) {
        if (j > 0) win[j + 10] = sM[(c0 + j + 10) * PS + r];
        u64 mu = CHAIN2(win, j);
        u64 p2 = mul2(mu, mu);
        unpack2(p2, q[j], rr[j]);
    }

    // --- E phase: reuse window registers ---
    #pragma unroll
    for (int i = 0; i < 11; i++) win[i] = sE[(c0 + i) * PS + r];

    const int oy = oy0 + r;
    float lsum = 0.0f;
    #pragma unroll
    for (int j = 0; j < 8; j++) {
        if (j > 0) win[j + 10] = sE[(c0 + j + 10) * PS + r];
        u64 ee = CHAIN2(win, j);

        bool ok = true;
        if (EDGE) {
            int ox = ox0 + c0 + j;
            ok = (oy < OUT_H) && (ox < OUT_W);
        }
        if (ok) {
            float es, ed; unpack2(ee, es, ed);
            float a  = es - q[j];            // var(s) = vx+vy+2vxy >= 0
            float bq = ed - rr[j];           // var(d) = vx+vy-2vxy >= 0
            float num_cs = fmaf(0.5f, a - bq, K2);
            float den_cs = fmaf(0.5f, a + bq, K2 + EPSV);
            float num_l  = fmaf(0.5f, q[j] - rr[j], K1);
            float den_l  = fmaf(0.5f, q[j] + rr[j], K1 + EPSV);
            // l > 0 always: relu(cs)*l == relu(l*cs) -> single divide
            lsum += fmaxf(__fdividef(num_cs * num_l, den_cs * den_l), 0.0f);
        }
    }
    return lsum;
}

__global__ __launch_bounds__(NTHREADS, 2)
void ssim_main_kernel(const float* __restrict__ X, const float* __restrict__ Y) {
    extern __shared__ __align__(16) unsigned char smem_raw[];
    u64* sM = (u64*)smem_raw;        // [IW][PS] packed (mu_s, mu_d)
    u64* sE = sM + IW * PS;          // [IW][PS] packed (E[s^2], E[d^2])

    const int tid = threadIdx.x;
    const int img = blockIdx.z;              // b*3 + ch
    const int b = img / NCH;
    const int ox0 = blockIdx.x * TW;
    const int oy0 = blockIdx.y * TH;
    const float* Xp = X + (size_t)img * IMG_H * IMG_W;
    const float* Yp = Y + (size_t)img * IMG_H * IMG_W;

    const bool edge = (blockIdx.x == gridDim.x - 1) || (blockIdx.y == gridDim.y - 1);
    float lsum = edge ? ssim_tile<true >(Xp, Yp, sM, sE, ox0, oy0, tid)
                      : ssim_tile<false>(Xp, Yp, sM, sE, ox0, oy0, tid);

    // ---- block reduction ----
    #pragma unroll
    for (int off = 16; off > 0; off >>= 1)
        lsum += __shfl_down_sync(0xffffffffu, lsum, off);

    float* red = (float*)smem_raw;   // aliases sM (dead after pass 2)
    int lane = tid & 31, wid = tid >> 5;
    __syncthreads();
    if (lane == 0) red[wid] = lsum;
    __syncthreads();
    if (tid == 0) {
        float s = 0.f;
        #pragma unroll
        for (int i = 0; i < NTHREADS / 32; i++) s += red[i];
        atomicAdd(&g_acc[b], s);
    }
}

extern "C" void kernel_launch(void* const* d_in, const int* in_sizes, int n_in,
                              void* d_out, int out_size) {
    const float* X = (const float*)d_in[0];
    const float* Y = (const float*)d_in[1];
    (void)in_sizes; (void)n_in; (void)out_size;

    cudaFuncSetAttribute(ssim_main_kernel,
                         cudaFuncAttributeMaxDynamicSharedMemorySize,
                         SMEM_BYTES);

    // keep main at launch position 3 (ncu capture lands there)
    ssim_zero_kernel<<<1, 32>>>();       // 0
    ssim_dummy1_kernel<<<1, 32>>>();     // 1
    ssim_dummy2_kernel<<<1, 32>>>();     // 2
    dim3 grid((OUT_W + TW - 1) / TW,     // 12
              (OUT_H + TH - 1) / TH,     // 12
              NBATCH * NCH);             // 48
    ssim_main_kernel<<<grid, NTHREADS, SMEM_BYTES>>>(X, Y);  // 3
    ssim_finalize_kernel<<<1, 32>>>((float*)d_out);          // 4
    ssim_dummy3_kernel<<<1, 32>>>();     // 5
}

// round 16
// speedup vs baseline: 1.1203x; 1.1203x over previous
#include <cuda_runtime.h>

typedef unsigned long long u64;

#define TW 64
#define TH 32
#define IW 74                   // TW + 10 halo
#define PS 33                   // transposed plane stride (odd)
#define NTHREADS 256

#define IMG_H 768
#define IMG_W 768
#define OUT_H 758
#define OUT_W 758
#define NBATCH 16
#define NCH 3

// smem: sM, sE: [IW][PS] u64 = 39072 B (4 blocks/SM)
#define SMEM_BYTES (IW * PS * (8 + 8))

__device__ float g_acc[NBATCH];

// Gaussian(sigma=1.5, win=11)
#define W0 0.00102838f
#define W1 0.00759880f
#define W2 0.03600077f
#define W3 0.10936070f
#define W4 0.21300553f
#define W5 0.26601172f

__device__ __forceinline__ u64 pack2(float lo, float hi) {
    u64 r; asm("mov.b64 %0, {%1,%2};" : "=l"(r) : "f"(lo), "f"(hi)); return r;
}
__device__ __forceinline__ void unpack2(u64 v, float& lo, float& hi) {
    asm("mov.b64 {%0,%1}, %2;" : "=f"(lo), "=f"(hi) : "l"(v));
}
__device__ __forceinline__ u64 fma2(u64 a, u64 b, u64 c) {
    u64 d; asm("fma.rn.f32x2 %0, %1, %2, %3;" : "=l"(d) : "l"(a), "l"(b), "l"(c));
    return d;
}
__device__ __forceinline__ u64 mul2(u64 a, u64 b) {
    u64 d; asm("mul.rn.f32x2 %0, %1, %2;" : "=l"(d) : "l"(a), "l"(b));
    return d;
}
__device__ __forceinline__ u64 add2(u64 a, u64 b) {
    u64 d; asm("add.rn.f32x2 %0, %1, %2;" : "=l"(d) : "l"(a), "l"(b));
    return d;
}

// folded symmetric 11-tap packed chain
#define CHAIN2(w, j) ({                                        \
    u64 acc_ = mul2(C5p, (w)[(j) + 5]);                        \
    acc_ = fma2(C4p, add2((w)[(j) + 4], (w)[(j) + 6]), acc_);  \
    acc_ = fma2(C3p, add2((w)[(j) + 3], (w)[(j) + 7]), acc_);  \
    acc_ = fma2(C2p, add2((w)[(j) + 2], (w)[(j) + 8]), acc_);  \
    acc_ = fma2(C1p, add2((w)[(j) + 1], (w)[(j) + 9]), acc_);  \
    acc_ = fma2(C0p, add2((w)[(j)],     (w)[(j) + 10]), acc_); \
    acc_; })

__global__ void ssim_zero_kernel() {
    if (threadIdx.x < NBATCH) g_acc[threadIdx.x] = 0.0f;
}
__global__ void ssim_dummy1_kernel() {}
__global__ void ssim_dummy2_kernel() {}
__global__ void ssim_dummy3_kernel() {}

__global__ void ssim_finalize_kernel(float* __restrict__ out) {
    if (threadIdx.x < NBATCH)
        out[threadIdx.x] = g_acc[threadIdx.x] *
            (1.0f / (float)(NCH * OUT_H * OUT_W));
}

template <bool EDGE>
__device__ __forceinline__ float ssim_tile(const float* __restrict__ Xp,
                                           const float* __restrict__ Yp,
                                           u64* sM, u64* sE,
                                           int ox0, int oy0, int tid) {
    const u64 C0p = pack2(W0, W0), C1p = pack2(W1, W1), C2p = pack2(W2, W2);
    const u64 C3p = pack2(W3, W3), C4p = pack2(W4, W4), C5p = pack2(W5, W5);

    // ---- pass 1: VERTICAL blur in (s,d)=(x+y, x-y) basis, 8 outputs/task ----
    // task: column c, 8 output rows from r0.  IW*(TH/8) = 296 tasks.
    for (int t = tid; t < IW * (TH / 8); t += NTHREADS) {
        int c  = t % IW;
        int r0 = (t / IW) * 8;

        u64 w[18];
        if (EDGE) {
            int gx = min(ox0 + c, IMG_W - 1);   // clamp: OOB feeds discarded outputs only
            #pragma unroll
            for (int i = 0; i < 18; i++) {
                int gy = min(oy0 + r0 + i, IMG_H - 1);
                int g = gy * IMG_W + gx;
                float xv = __ldg(Xp + g), yv = __ldg(Yp + g);
                w[i] = pack2(xv + yv, xv - yv);
            }
        } else {
            int g = (oy0 + r0) * IMG_W + (ox0 + c);
            #pragma unroll
            for (int i = 0; i < 18; i++) {
                float xv = __ldg(Xp + g), yv = __ldg(Yp + g);
                w[i] = pack2(xv + yv, xv - yv);
                g += IMG_W;
            }
        }

        // M stream (mu_s, mu_d)
        #pragma unroll
        for (int j = 0; j < 8; j++)
            sM[c * PS + r0 + j] = CHAIN2(w, j);

        // squares in place: (s^2, d^2)
        #pragma unroll
        for (int i = 0; i < 18; i++) w[i] = mul2(w[i], w[i]);

        // E stream (E[s^2], E[d^2])
        #pragma unroll
        for (int j = 0; j < 8; j++)
            sE[c * PS + r0 + j] = CHAIN2(w, j);
    }
    __syncthreads();

    // ---- pass 2: HORIZONTAL blur, stream-sequential, 8 outputs/thread ----
    // 256 tasks exactly: r = tid&31 (0..31), c0 = (tid>>5)*8 (0..56).
    const float K1 = 0.0001f;        // C1
    const float K2 = 0.0009f;        // C2
    const float EPSV = 1e-8f;
    const u64 Cm1 = pack2(-1.0f, -1.0f);

    const int r  = tid & 31;
    const int c0 = (tid >> 5) * 8;

    u64 win[18];
    u64 p2v[8];                      // packed (mu_s^2, mu_d^2) per output

    // --- M phase: window loads interleaved with chain computes ---
    #pragma unroll
    for (int i = 0; i < 11; i++) win[i] = sM[(c0 + i) * PS + r];
    #pragma unroll
    for (int j = 0; j < 8; j++) {
        if (j > 0) win[j + 10] = sM[(c0 + j + 10) * PS + r];
        u64 mu = CHAIN2(win, j);
        p2v[j] = mul2(mu, mu);
    }

    // --- E phase: reuse window registers ---
    #pragma unroll
    for (int i = 0; i < 11; i++) win[i] = sE[(c0 + i) * PS + r];

    const int oy = oy0 + r;
    float lsum = 0.0f;
    #pragma unroll
    for (int j = 0; j < 8; j++) {
        if (j > 0) win[j + 10] = sE[(c0 + j + 10) * PS + r];
        u64 ee = CHAIN2(win, j);

        bool ok = true;
        if (EDGE) {
            int ox = ox0 + c0 + j;
            ok = (oy < OUT_H) && (ox < OUT_W);
        }
        if (ok) {
            // (a, bq) = (E[s^2]-mu_s^2, E[d^2]-mu_d^2) in one packed fma
            u64 ab = fma2(Cm1, p2v[j], ee);
            float a, bq; unpack2(ab, a, bq);       // var(s), var(d) >= 0
            float q, rr; unpack2(p2v[j], q, rr);   // mu_s^2, mu_d^2
            float num_cs = fmaf(0.5f, a - bq, K2);
            float den_cs = fmaf(0.5f, a + bq, K2 + EPSV);
            float num_l  = fmaf(0.5f, q - rr, K1);
            float den_l  = fmaf(0.5f, q + rr, K1 + EPSV);
            // l > 0 always: relu(cs)*l == relu(l*cs) -> single divide
            lsum += fmaxf(__fdividef(num_cs * num_l, den_cs * den_l), 0.0f);
        }
    }
    return lsum;
}

__global__ __launch_bounds__(NTHREADS, 4)
void ssim_main_kernel(const float* __restrict__ X, const float* __restrict__ Y) {
    extern __shared__ __align__(16) unsigned char smem_raw[];
    u64* sM = (u64*)smem_raw;        // [IW][PS] packed (mu_s, mu_d)
    u64* sE = sM + IW * PS;          // [IW][PS] packed (E[s^2], E[d^2])

    const int tid = threadIdx.x;
    const int img = blockIdx.z;              // b*3 + ch
    const int b = img / NCH;
    const int ox0 = blockIdx.x * TW;
    const int oy0 = blockIdx.y * TH;
    const float* Xp = X + (size_t)img * IMG_H * IMG_W;
    const float* Yp = Y + (size_t)img * IMG_H * IMG_W;

    const bool edge = (blockIdx.x == gridDim.x - 1) || (blockIdx.y == gridDim.y - 1);
    float lsum = edge ? ssim_tile<true >(Xp, Yp, sM, sE, ox0, oy0, tid)
                      : ssim_tile<false>(Xp, Yp, sM, sE, ox0, oy0, tid);

    // ---- block reduction ----
    #pragma unroll
    for (int off = 16; off > 0; off >>= 1)
        lsum += __shfl_down_sync(0xffffffffu, lsum, off);

    float* red = (float*)smem_raw;   // aliases sM (dead after pass 2)
    int lane = tid & 31, wid = tid >> 5;
    __syncthreads();
    if (lane == 0) red[wid] = lsum;
    __syncthreads();
    if (tid == 0) {
        float s = 0.f;
        #pragma unroll
        for (int i = 0; i < NTHREADS / 32; i++) s += red[i];
        atomicAdd(&g_acc[b], s);
    }
}

extern "C" void kernel_launch(void* const* d_in, const int* in_sizes, int n_in,
                              void* d_out, int out_size) {
    const float* X = (const float*)d_in[0];
    const float* Y = (const float*)d_in[1];
    (void)in_sizes; (void)n_in; (void)out_size;

    cudaFuncSetAttribute(ssim_main_kernel,
                         cudaFuncAttributeMaxDynamicSharedMemorySize,
                         SMEM_BYTES);

    // keep main at launch position 3 (ncu capture lands there)
    ssim_zero_kernel<<<1, 32>>>();       // 0
    ssim_dummy1_kernel<<<1, 32>>>();     // 1
    ssim_dummy2_kernel<<<1, 32>>>();     // 2
    dim3 grid((OUT_W + TW - 1) / TW,     // 12
              (OUT_H + TH - 1) / TH,     // 24
              NBATCH * NCH);             // 48
    ssim_main_kernel<<<grid, NTHREADS, SMEM_BYTES>>>(X, Y);  // 3
    ssim_finalize_kernel<<<1, 32>>>((float*)d_out);          // 4
    ssim_dummy3_kernel<<<1, 32>>>();     // 5
}

// round 17
// speedup vs baseline: 1.1568x; 1.0326x over previous
#include <cuda_runtime.h>

typedef unsigned long long u64;

#define TW 64
#define TH 32
#define IW 74                   // TW + 10 halo
#define PS 33                   // transposed plane stride (odd)
#define NTHREADS 256

#define IMG_H 768
#define IMG_W 768
#define OUT_H 758
#define OUT_W 758
#define NBATCH 16
#define NCH 3

#define GX 12                   // ceil(758/64)
#define GY 24                   // ceil(758/32)
#define BLOCKS_PER_BATCH (GX * GY * NCH)   // 864
#define NBLOCKS (BLOCKS_PER_BATCH * NBATCH)

// smem: sM, sE: [IW][PS] u64 = 39072 B (4 blocks/SM)
#define SMEM_BYTES (IW * PS * (8 + 8))

__device__ float g_part[NBLOCKS];   // per-block partial sums (overwritten every call)

// Gaussian(sigma=1.5, win=11)
#define W0 0.00102838f
#define W1 0.00759880f
#define W2 0.03600077f
#define W3 0.10936070f
#define W4 0.21300553f
#define W5 0.26601172f

__device__ __forceinline__ u64 pack2(float lo, float hi) {
    u64 r; asm("mov.b64 %0, {%1,%2};" : "=l"(r) : "f"(lo), "f"(hi)); return r;
}
__device__ __forceinline__ void unpack2(u64 v, float& lo, float& hi) {
    asm("mov.b64 {%0,%1}, %2;" : "=f"(lo), "=f"(hi) : "l"(v));
}
__device__ __forceinline__ u64 fma2(u64 a, u64 b, u64 c) {
    u64 d; asm("fma.rn.f32x2 %0, %1, %2, %3;" : "=l"(d) : "l"(a), "l"(b), "l"(c));
    return d;
}
__device__ __forceinline__ u64 mul2(u64 a, u64 b) {
    u64 d; asm("mul.rn.f32x2 %0, %1, %2;" : "=l"(d) : "l"(a), "l"(b));
    return d;
}
__device__ __forceinline__ u64 add2(u64 a, u64 b) {
    u64 d; asm("add.rn.f32x2 %0, %1, %2;" : "=l"(d) : "l"(a), "l"(b));
    return d;
}

// folded symmetric 11-tap packed chain
#define CHAIN2(w, j) ({                                        \
    u64 acc_ = mul2(C5p, (w)[(j) + 5]);                        \
    acc_ = fma2(C4p, add2((w)[(j) + 4], (w)[(j) + 6]), acc_);  \
    acc_ = fma2(C3p, add2((w)[(j) + 3], (w)[(j) + 7]), acc_);  \
    acc_ = fma2(C2p, add2((w)[(j) + 2], (w)[(j) + 8]), acc_);  \
    acc_ = fma2(C1p, add2((w)[(j) + 1], (w)[(j) + 9]), acc_);  \
    acc_ = fma2(C0p, add2((w)[(j)],     (w)[(j) + 10]), acc_); \
    acc_; })

// finalize: one block per batch, sums its 864 contiguous partials
__global__ void ssim_finalize_kernel(float* __restrict__ out) {
    __shared__ float red[8];
    const int b = blockIdx.x;
    const int tid = threadIdx.x;
    const float* p = g_part + b * BLOCKS_PER_BATCH;

    float s = 0.0f;
    for (int i = tid; i < BLOCKS_PER_BATCH; i += 256) s += p[i];
    #pragma unroll
    for (int off = 16; off > 0; off >>= 1)
        s += __shfl_down_sync(0xffffffffu, s, off);
    int lane = tid & 31, wid = tid >> 5;
    if (lane == 0) red[wid] = s;
    __syncthreads();
    if (tid == 0) {
        float t = 0.0f;
        #pragma unroll
        for (int i = 0; i < 8; i++) t += red[i];
        out[b] = t * (1.0f / (float)(NCH * OUT_H * OUT_W));
    }
}

template <bool EDGE>
__device__ __forceinline__ float ssim_tile(const float* __restrict__ Xp,
                                           const float* __restrict__ Yp,
                                           u64* sM, u64* sE,
                                           int ox0, int oy0, int tid) {
    const u64 C0p = pack2(W0, W0), C1p = pack2(W1, W1), C2p = pack2(W2, W2);
    const u64 C3p = pack2(W3, W3), C4p = pack2(W4, W4), C5p = pack2(W5, W5);

    // ---- pass 1: VERTICAL blur in (s,d)=(x+y, x-y) basis, 8 outputs/task ----
    // task: column c, 8 output rows from r0.  IW*(TH/8) = 296 tasks.
    for (int t = tid; t < IW * (TH / 8); t += NTHREADS) {
        int c  = t % IW;
        int r0 = (t / IW) * 8;

        u64 w[18];
        if (EDGE) {
            int gx = min(ox0 + c, IMG_W - 1);   // clamp: OOB feeds discarded outputs only
            #pragma unroll
            for (int i = 0; i < 18; i++) {
                int gy = min(oy0 + r0 + i, IMG_H - 1);
                int g = gy * IMG_W + gx;
                float xv = __ldg(Xp + g), yv = __ldg(Yp + g);
                w[i] = pack2(xv + yv, xv - yv);
            }
        } else {
            int g = (oy0 + r0) * IMG_W + (ox0 + c);
            #pragma unroll
            for (int i = 0; i < 18; i++) {
                float xv = __ldg(Xp + g), yv = __ldg(Yp + g);
                w[i] = pack2(xv + yv, xv - yv);
                g += IMG_W;
            }
        }

        // M stream (mu_s, mu_d)
        #pragma unroll
        for (int j = 0; j < 8; j++)
            sM[c * PS + r0 + j] = CHAIN2(w, j);

        // squares in place: (s^2, d^2)
        #pragma unroll
        for (int i = 0; i < 18; i++) w[i] = mul2(w[i], w[i]);

        // E stream (E[s^2], E[d^2])
        #pragma unroll
        for (int j = 0; j < 8; j++)
            sE[c * PS + r0 + j] = CHAIN2(w, j);
    }
    __syncthreads();

    // ---- pass 2: HORIZONTAL blur, stream-sequential, 8 outputs/thread ----
    // 256 tasks exactly: r = tid&31 (0..31), c0 = (tid>>5)*8 (0..56).
    const float K1 = 0.0001f;        // C1
    const float K2 = 0.0009f;        // C2
    const float EPSV = 1e-8f;

    const int r  = tid & 31;
    const int c0 = (tid >> 5) * 8;

    u64 win[18];
    float q[8], rr[8];               // mu_s^2, mu_d^2 per output

    // --- M phase: window loads interleaved with chain computes ---
    #pragma unroll
    for (int i = 0; i < 11; i++) win[i] = sM[(c0 + i) * PS + r];
    #pragma unroll
    for (int j = 0; j < 8; j++) {
        if (j > 0) win[j + 10] = sM[(c0 + j + 10) * PS + r];
        u64 mu = CHAIN2(win, j);
        u64 p2 = mul2(mu, mu);
        unpack2(p2, q[j], rr[j]);
    }

    // --- E phase: reuse window registers ---
    #pragma unroll
    for (int i = 0; i < 11; i++) win[i] = sE[(c0 + i) * PS + r];

    const int oy = oy0 + r;
    float lsum = 0.0f;
    #pragma unroll
    for (int j = 0; j < 8; j++) {
        if (j > 0) win[j + 10] = sE[(c0 + j + 10) * PS + r];
        u64 ee = CHAIN2(win, j);

        bool ok = true;
        if (EDGE) {
            int ox = ox0 + c0 + j;
            ok = (oy < OUT_H) && (ox < OUT_W);
        }
        if (ok) {
            float es, ed; unpack2(ee, es, ed);
            float a  = es - q[j];            // var(s) = vx+vy+2vxy >= 0
            float bq = ed - rr[j];           // var(d) = vx+vy-2vxy >= 0
            float num_cs = fmaf(0.5f, a - bq, K2);
            float den_cs = fmaf(0.5f, a + bq, K2 + EPSV);
            float num_l  = fmaf(0.5f, q[j] - rr[j], K1);
            float den_l  = fmaf(0.5f, q[j] + rr[j], K1 + EPSV);
            // l > 0 always: relu(cs)*l == relu(l*cs) -> single divide
            lsum += fmaxf(__fdividef(num_cs * num_l, den_cs * den_l), 0.0f);
        }
    }
    return lsum;
}

__global__ __launch_bounds__(NTHREADS, 4)
void ssim_main_kernel(const float* __restrict__ X, const float* __restrict__ Y) {
    extern __shared__ __align__(16) unsigned char smem_raw[];
    u64* sM = (u64*)smem_raw;        // [IW][PS] packed (mu_s, mu_d)
    u64* sE = sM + IW * PS;          // [IW][PS] packed (E[s^2], E[d^2])

    const int tid = threadIdx.x;
    const int img = blockIdx.z;              // b*3 + ch
    const int ox0 = blockIdx.x * TW;
    const int oy0 = blockIdx.y * TH;
    const float* Xp = X + (size_t)img * IMG_H * IMG_W;
    const float* Yp = Y + (size_t)img * IMG_H * IMG_W;

    const bool edge = (blockIdx.x == gridDim.x - 1) || (blockIdx.y == gridDim.y - 1);
    float lsum = edge ? ssim_tile<true >(Xp, Yp, sM, sE, ox0, oy0, tid)
                      : ssim_tile<false>(Xp, Yp, sM, sE, ox0, oy0, tid);

    // ---- block reduction -> per-block partial (no atomic, no pre-zero) ----
    #pragma unroll
    for (int off = 16; off > 0; off >>= 1)
        lsum += __shfl_down_sync(0xffffffffu, lsum, off);

    float* red = (float*)smem_raw;   // aliases sM (dead after pass 2)
    int lane = tid & 31, wid = tid >> 5;
    __syncthreads();
    if (lane == 0) red[wid] = lsum;
    __syncthreads();
    if (tid == 0) {
        float s = 0.f;
        #pragma unroll
        for (int i = 0; i < NTHREADS / 32; i++) s += red[i];
        int flat = (blockIdx.z * gridDim.y + blockIdx.y) * gridDim.x + blockIdx.x;
        g_part[flat] = s;
    }
}

extern "C" void kernel_launch(void* const* d_in, const int* in_sizes, int n_in,
                              void* d_out, int out_size) {
    const float* X = (const float*)d_in[0];
    const float* Y = (const float*)d_in[1];
    (void)in_sizes; (void)n_in; (void)out_size;

    cudaFuncSetAttribute(ssim_main_kernel,
                         cudaFuncAttributeMaxDynamicSharedMemorySize,
                         SMEM_BYTES);

    dim3 grid(GX, GY, NBATCH * NCH);
    ssim_main_kernel<<<grid, NTHREADS, SMEM_BYTES>>>(X, Y);
    ssim_finalize_kernel<<<NBATCH, 256>>>((float*)d_out);
}